// round 10
// baseline (speedup 1.0000x reference)
#include <cuda_runtime.h>
#include <cuda_fp16.h>
#include <math.h>
#include <stdint.h>

// Problem constants
#define T_     128
#define NSEQ   256          // B*S
#define EMBED  512
#define UNITS  512
#define G4     2048         // 4*UNITS
#define NZ     4096         // both directions
#define NCTA   128
#define GSZ    16           // CTAs per dependency group (dir, rb)

// ---------------- scratch (device globals) ---------------------------------
// xW packed per dir as [hcol*4 + gate] (gates adjacent -> uint4 per 2 hcols)
__device__ __half   g_xW[(size_t)NSEQ * T_ * NZ];
__device__ __half   g_h16[2][2][NSEQ * UNITS];     // fp16 h, [parity][dir]
__device__ uint32_t g_Upk[2 * 16 * 32768];         // fp16 frag-packed U per (dir,cb) slice
__device__ uint32_t g_Wpk[32 * 32768];             // fp16 frag-packed [W_f|W_b]

struct alignas(128) Bar { unsigned cnt; unsigned gen; };
__device__ Bar g_bars[8];                          // fallback barrier, one per group

__device__ __forceinline__ float tanh_fast(float x) {
    float r; asm("tanh.approx.f32 %0, %1;" : "=f"(r) : "f"(x)); return r;
}
__device__ __forceinline__ float sigm_fast(float x) {
    return fmaf(tanh_fast(0.5f * x), 0.5f, 0.5f);
}

#define CLUSTER_ARRIVE() asm volatile("barrier.cluster.arrive.release.aligned;" ::: "memory")
#define CLUSTER_WAIT()   asm volatile("barrier.cluster.wait.acquire.aligned;" ::: "memory")

// ---------------- pack U into fp16 mma.sync fragment order -----------------
// Slice (dir, cb): B[k][n] = U[k][g*512 + cb*32 + hl], n = g*32+hl (128 zcols).
// Word layout: [kb 32][np 8][lane 32][4 words]; word (sub*2+wi) holds
// k = kb*16 + wi*8 + 2qc (+1), n = (np*2+sub)*8 + qr. lane = qr*4+qc.
__global__ __launch_bounds__(256) void prep_U(
    const float* __restrict__ U_f, const float* __restrict__ U_b)
{
    int widx  = blockIdx.x * 256 + threadIdx.x;   // < 2^20
    int word  = widx & 32767;
    int slice = widx >> 15;
    int dir = slice >> 4, cb = slice & 15;
    int kb   = word >> 10;
    int np   = (word >> 7) & 7;
    int lane = (word >> 2) & 31;
    int q    = word & 3;
    int sub = q >> 1, wi = q & 1;
    int qr = lane >> 2, qc = lane & 3;
    int n = (np * 2 + sub) * 8 + qr;
    int k = kb * 16 + wi * 8 + 2 * qc;
    int col = (n >> 5) * 512 + cb * 32 + (n & 31);
    const float* U = dir ? U_b : U_f;
    float lo = U[(size_t)k * G4 + col];
    float hi = U[(size_t)(k + 1) * G4 + col];
    half2 h2 = __floats2half2_rn(lo, hi);
    g_Upk[widx] = *(uint32_t*)&h2;
}

// ---------------- pack [W_f|W_b] into same fragment order ------------------
__global__ __launch_bounds__(256) void prep_W(
    const float* __restrict__ W_f, const float* __restrict__ W_b)
{
    int widx  = blockIdx.x * 256 + threadIdx.x;
    int word  = widx & 32767;
    int nb    = widx >> 15;
    int kb   = word >> 10;
    int np   = (word >> 7) & 7;
    int lane = (word >> 2) & 31;
    int q    = word & 3;
    int sub = q >> 1, wi = q & 1;
    int qr = lane >> 2, qc = lane & 3;
    int nl = (np * 2 + sub) * 8 + qr;
    int k  = kb * 16 + wi * 8 + 2 * qc;
    int c  = nb * 128 + nl;
    const float* W = (c < G4) ? (W_f + c) : (W_b + c - G4);
    float lo = W[(size_t)k * G4];
    float hi = W[(size_t)(k + 1) * G4];
    half2 h2 = __floats2half2_rn(lo, hi);
    g_Wpk[widx] = *(uint32_t*)&h2;
}

// ---------------- MMA helpers ----------------------------------------------
#define MMA16816(d, a, b0v, b1v)                                              \
    asm volatile(                                                             \
        "mma.sync.aligned.m16n8k16.row.col.f32.f16.f16.f32 "                  \
        "{%0,%1,%2,%3},{%4,%5,%6,%7},{%8,%9},{%0,%1,%2,%3};"                  \
        : "+f"(d[0]), "+f"(d[1]), "+f"(d[2]), "+f"(d[3])                      \
        : "r"(a[0]), "r"(a[1]), "r"(a[2]), "r"(a[3]), "r"(b0v), "r"(b1v))

#define LDSM4(r, addr)                                                        \
    asm volatile("ldmatrix.sync.aligned.m8n8.x4.shared.b16 "                  \
                 "{%0,%1,%2,%3}, [%4];"                                       \
                 : "=r"(r[0]), "=r"(r[1]), "=r"(r[2]), "=r"(r[3])             \
                 : "r"(addr))

extern __shared__ char smem_dyn[];

// ---------------- Phase 1: fused gather + fp16 tensor-core GEMM ------------
#define ESTR 520

__global__ __launch_bounds__(256, 1) void embed_mma(
    const int* __restrict__ x, const float* __restrict__ emb,
    const float* __restrict__ b_f, const float* __restrict__ b_b)
{
    __shared__ int ids_s[128];
    __half* hA = (__half*)smem_dyn;

    const int tid  = threadIdx.x;
    const int lane = tid & 31;
    const int wid  = tid >> 5;
    const int wm   = wid >> 1;
    const int wn   = wid & 1;
    const int qr = lane >> 2, qc = lane & 3;
    const int mBase = blockIdx.y * 128;
    const int nb    = blockIdx.x * 2 + wn;

    if (tid < 128) ids_s[tid] = x[mBase + tid];
    __syncthreads();

    {
        int row = tid >> 1, seg = tid & 1;
        const float* src = emb + (size_t)ids_s[row] * EMBED + seg * 256;
        __half* d = hA + row * ESTR + seg * 256;
        #pragma unroll
        for (int i = 0; i < 64; i++) {
            float4 v = *(const float4*)(src + i * 4);
            *(half2*)(d + i * 4)     = __floats2half2_rn(v.x, v.y);
            *(half2*)(d + i * 4 + 2) = __floats2half2_rn(v.z, v.w);
        }
    }
    __syncthreads();

    int lm_row = (lane & 7) + ((lane >> 3) & 1) * 8;
    int lm_kh  = (lane >> 4) * 8;
    uint32_t hA_s = (uint32_t)__cvta_generic_to_shared(hA);
    uint32_t lmaddr0 = hA_s + (uint32_t)(((wm * 32 + 0  + lm_row) * ESTR + lm_kh) * 2);
    uint32_t lmaddr1 = hA_s + (uint32_t)(((wm * 32 + 16 + lm_row) * ESTR + lm_kh) * 2);

    const uint32_t* gW = g_Wpk + (size_t)nb * 32768;

    float acc[2][16][4];
    #pragma unroll
    for (int mt = 0; mt < 2; mt++)
        #pragma unroll
        for (int j = 0; j < 16; j++)
            #pragma unroll
            for (int r = 0; r < 4; r++) acc[mt][j][r] = 0.f;

    #pragma unroll 2
    for (int kb = 0; kb < 32; kb++) {
        uint32_t a0[4], a1[4];
        LDSM4(a0, lmaddr0 + kb * 32);
        LDSM4(a1, lmaddr1 + kb * 32);
        uint4 Bv[8];
        #pragma unroll
        for (int np = 0; np < 8; np++)
            Bv[np] = *(const uint4*)&gW[(((kb * 8 + np) * 32 + lane) << 2)];
        #pragma unroll
        for (int j = 0; j < 16; j++) {
            uint32_t b0 = (j & 1) ? Bv[j >> 1].z : Bv[j >> 1].x;
            uint32_t b1 = (j & 1) ? Bv[j >> 1].w : Bv[j >> 1].y;
            MMA16816(acc[0][j], a0, b0, b1);
            MMA16816(acc[1][j], a1, b0, b1);
        }
    }

    // Epilogue: add bias, store fp16 z packed as [hcol*4 + gate]
    const float* bp = (nb < 16) ? (b_f + nb * 128) : (b_b + nb * 128 - G4);
    const int dirW = nb >> 4;
    const int nOff = (nb & 15) * 128;
    #pragma unroll
    for (int mt = 0; mt < 2; mt++) {
        #pragma unroll
        for (int j = 0; j < 16; j++) {
            int row = mBase + wm * 32 + mt * 16 + qr;
            int cl  = j * 8 + qc * 2;
            int n0  = nOff + cl;
            int g0  = n0 >> 9, h0 = n0 & 511;
            float bx = bp[cl], by = bp[cl + 1];
            size_t pk0 = (size_t)dirW * 2048 + h0 * 4 + g0;
            g_xW[(size_t)row * NZ + pk0]           = __float2half(acc[mt][j][0] + bx);
            g_xW[(size_t)row * NZ + pk0 + 4]       = __float2half(acc[mt][j][1] + by);
            g_xW[(size_t)(row + 8) * NZ + pk0]     = __float2half(acc[mt][j][2] + bx);
            g_xW[(size_t)(row + 8) * NZ + pk0 + 4] = __float2half(acc[mt][j][3] + by);
        }
    }
}

// ---------------- Phase 2: persistent bidirectional LSTM -------------------
// 128 CTAs x 512 thr. bid = gid*16 + cb, gid = dir*4 + rb (cluster = group).
// CTA: 64 rows x 128 zcols; all 4 gates in-thread; register state; MUFU epi.
__global__ __launch_bounds__(512, 1) void lstm_persist(
    const int* __restrict__ x, float* __restrict__ out, int use_cluster)
{
    uint32_t* uB  = (uint32_t*)smem_dyn;           // 128 KB
    char*     hAb = smem_dyn + 131072;             // 64 KB swizzled A staging

    const int tid  = threadIdx.x;
    const int lane = tid & 31;
    const int wid  = tid >> 5;                     // 0..15
    const int bid  = blockIdx.x;
    const int gid  = bid >> 4;                     // 0..7
    const int dir  = gid >> 2;
    const int rb   = gid & 3;
    const int cb   = bid & 15;
    const int rBase  = rb * 64;
    const int cbBase = cb * 32;

    // Load U slice once (resident for all steps)
    {
        const uint4* src = (const uint4*)(g_Upk + (size_t)(dir * 16 + cb) * 32768);
        uint4* dst = (uint4*)uB;
        #pragma unroll
        for (int i = 0; i < 16; i++) dst[i * 512 + tid] = src[i * 512 + tid];
    }

    const int wm = wid >> 2;          // 0..3 : 16 rows
    const int wn = wid & 3;           // 0..3 : 8 hcols each
    const int qr = lane >> 2, qc = lane & 3;
    const int woff = wn >> 1;
    const int sub2 = (wn & 1) * 2;
    const int hc = wn * 8 + 2 * qc;   // local hcol (even)

    // Register-resident state: [e(row) * 2 + cc(col)]
    float creg[4], hreg[4];
    #pragma unroll
    for (int e = 0; e < 4; e++) { creg[e] = 0.f; hreg[e] = 0.f; }
    // Zero own h16[0] slice: 64 rows x 32 cols fp16
    {
        int row = rBase + (tid >> 3);
        int seg = (tid & 7) * 4;
        *(uint2*)&g_h16[0][dir][row * UNITS + cbBase + seg] = make_uint2(0, 0);
    }

    // ldmatrix swizzled base: addr(kb) = C0 ^ (kb*32)
    const int lrow = wm * 16 + (lane & 7) + ((lane >> 3) & 1) * 8;
    const int hi   = lane >> 4;
    const int r7   = lrow & 7;
    uint32_t hA_s = (uint32_t)__cvta_generic_to_shared(hAb);
    const uint32_t C0 = hA_s + (uint32_t)(lrow * 1024 + ((hi ^ (r7 & 1)) * 16) + (r7 >> 1) * 32);

    // staging thread mapping
    const int srow = tid >> 3, ssub = tid & 7, sr7 = srow & 7;

    unsigned curgen = 0;
    uint4 xv[2];
    bool  mreg[2];

    for (int sstep = 0; sstep < T_; sstep++) {
        const int parity = sstep & 1;
        const int t = dir ? (T_ - 1 - sstep) : sstep;
        const __half* h16cur = g_h16[parity][dir];
        __half*       h16nxt = g_h16[parity ^ 1][dir];

        // ---- barrier arrive (publishes prev h / init zeros) ----
        if (use_cluster) {
            CLUSTER_ARRIVE();
        } else {
            __syncthreads();
            if (tid == 0) {
                __threadfence();
                volatile unsigned* genp = &g_bars[gid].gen;
                curgen = *genp;
                if (atomicAdd(&g_bars[gid].cnt, 1u) == GSZ - 1) {
                    g_bars[gid].cnt = 0;
                    __threadfence();
                    *genp = curgen + 1;
                }
            }
        }

        // ---- prefetch xW (packed: one uint4 = 2 hcols x 4 gates) + mask ----
        #pragma unroll
        for (int e = 0; e < 2; e++) {
            int s = rBase + wm * 16 + qr + e * 8;
            xv[e] = __ldcs((const uint4*)(g_xW + ((size_t)s * T_ + t) * NZ
                                          + dir * 2048 + (size_t)(cbBase + hc) * 4));
            mreg[e] = (x[s * T_ + t] != 0);
        }

        // ---- barrier wait ----
        if (use_cluster) {
            CLUSTER_WAIT();
        } else {
            if (tid == 0) {
                volatile unsigned* genp = &g_bars[gid].gen;
                while (*genp == curgen) { __nanosleep(20); }
                __threadfence();
            }
            __syncthreads();
        }

        // ---- stage h tile (64 rows x 512 halves) -> swizzled SMEM ----
        {
            const __half* src = h16cur + (size_t)(rBase + srow) * UNITS;
            #pragma unroll
            for (int i = 0; i < 8; i++) {
                int u = i * 8 + ssub;
                uint4 v = *(const uint4*)(src + u * 8);
                *(uint4*)(hAb + srow * 1024 + ((u ^ sr7) * 16)) = v;
            }
        }
        __syncthreads();

        // ---- K loop: z = h @ U, software-pipelined ----
        float acc[4][4];
        #pragma unroll
        for (int g = 0; g < 4; g++)
            #pragma unroll
            for (int r = 0; r < 4; r++) acc[g][r] = 0.f;

        uint32_t aP[4];
        uint2    bP[4];
        LDSM4(aP, C0);
        #pragma unroll
        for (int g = 0; g < 4; g++)
            bP[g] = *(const uint2*)&uB[(((g * 2 + woff) * 32 + lane) << 2) + sub2];

        #pragma unroll
        for (int kb = 0; kb < 32; kb++) {
            uint32_t aC[4] = { aP[0], aP[1], aP[2], aP[3] };
            uint2    bC[4] = { bP[0], bP[1], bP[2], bP[3] };
            if (kb + 1 < 32) {
                LDSM4(aP, C0 ^ (uint32_t)((kb + 1) << 5));
                #pragma unroll
                for (int g = 0; g < 4; g++)
                    bP[g] = *(const uint2*)&uB[((((kb + 1) * 8 + g * 2 + woff) * 32 + lane) << 2) + sub2];
            }
            #pragma unroll
            for (int g = 0; g < 4; g++)
                MMA16816(acc[g], aC, bC[g].x, bC[g].y);
        }

        // ---- fused gate epilogue on registers; publish h fp16 ----
        #pragma unroll
        for (int e = 0; e < 2; e++) {
            const half2* ph = (const half2*)&xv[e];
            float hv[2];
            #pragma unroll
            for (int cc = 0; cc < 2; cc++) {
                int idx = e * 2 + cc;
                float2 p0 = __half22float2(ph[cc * 2]);
                float2 p1 = __half22float2(ph[cc * 2 + 1]);
                float zi = acc[0][idx] + p0.x;
                float zf = acc[1][idx] + p0.y;
                float zg = acc[2][idx] + p1.x;
                float zo = acc[3][idx] + p1.y;
                float ig = sigm_fast(zi), fg = sigm_fast(zf);
                float gg = tanh_fast(zg), og = sigm_fast(zo);
                float cnew = fg * creg[idx] + ig * gg;
                float hnew = og * tanh_fast(cnew);
                if (mreg[e]) { creg[idx] = cnew; hreg[idx] = hnew; }
                hv[cc] = hreg[idx];
            }
            int row = rBase + wm * 16 + qr + e * 8;
            *(half2*)&h16nxt[row * UNITS + cbBase + hc] = __floats2half2_rn(hv[0], hv[1]);
        }
        __syncthreads();   // hAb stable until all warps finish K loop reads
    }

    // Output straight from registers
    #pragma unroll
    for (int e = 0; e < 2; e++) {
        int s = rBase + wm * 16 + qr + e * 8;
        *(float2*)&out[s * 1024 + dir * 512 + cbBase + hc] =
            make_float2(hreg[e * 2], hreg[e * 2 + 1]);
    }
}

// ---------------- launcher -------------------------------------------------
extern "C" void kernel_launch(void* const* d_in, const int* in_sizes, int n_in,
                              void* d_out, int out_size)
{
    const int*   x   = (const int*)  d_in[0];
    const float* emb = (const float*)d_in[1];
    const float* W_f = (const float*)d_in[2];
    const float* U_f = (const float*)d_in[3];
    const float* b_f = (const float*)d_in[4];
    const float* W_b = (const float*)d_in[5];
    const float* U_b = (const float*)d_in[6];
    const float* b_b = (const float*)d_in[7];
    float* out = (float*)d_out;

    cudaFuncSetAttribute(embed_mma,
                         cudaFuncAttributeMaxDynamicSharedMemorySize, 133120);
    cudaFuncSetAttribute(lstm_persist,
                         cudaFuncAttributeMaxDynamicSharedMemorySize, 196608);
    cudaFuncSetAttribute(lstm_persist,
                         cudaFuncAttributeNonPortableClusterSizeAllowed, 1);

    prep_U<<<(2 * 16 * 32768) / 256, 256>>>(U_f, U_b);
    prep_W<<<(32 * 32768) / 256, 256>>>(W_f, W_b);
    embed_mma<<<dim3(16, 256), 256, 133120>>>(x, emb, b_f, b_b);

    // Try cluster launch (16-CTA clusters = dependency groups); validated via
    // occupancy query each call (deterministic). Fallback: atomic barrier.
    cudaLaunchAttribute attrs[1];
    attrs[0].id = cudaLaunchAttributeClusterDimension;
    attrs[0].val.clusterDim = {GSZ, 1, 1};
    cudaLaunchConfig_t cfg = {};
    cfg.gridDim = dim3(NCTA, 1, 1);
    cfg.blockDim = dim3(512, 1, 1);
    cfg.dynamicSmemBytes = 196608;
    cfg.stream = 0;
    cfg.attrs = attrs;
    cfg.numAttrs = 1;

    int nclust = 0;
    cudaError_t qe = cudaOccupancyMaxActiveClusters(&nclust, lstm_persist, &cfg);
    if (qe == cudaSuccess && nclust >= NCTA / GSZ) {
        cudaLaunchKernelEx(&cfg, lstm_persist, x, out, 1);
    } else {
        (void)cudaGetLastError();   // clear query error
        lstm_persist<<<NCTA, 512, 196608>>>(x, out, 0);
    }
}